// round 5
// baseline (speedup 1.0000x reference)
#include <cuda_runtime.h>
#include <cstdint>
#include <cstddef>

#define NTOK 2048
#define DIN  1024
#define DHID 4096
#define DOUT 1024
#define NEXP 8
#define CAP  2048

// ---------------- scratch (static device globals; no allocs allowed) ----------------
__device__ int   g_cnt[NEXP];
__device__ int   g_tok_of_row[NEXP * CAP];
__device__ int   g_slot_row[NTOK * 2];
__device__ float g_slot_w[NTOK * 2];
__device__ float g_X[(size_t)NTOK * DIN];         // tf32-rounded copy of x
__device__ float g_H[(size_t)NEXP * CAP * DHID];  // 256 MB (tf32-rounded)
__device__ float g_Y[(size_t)NEXP * CAP * DOUT];  // 64 MB

// ---------------- helpers ----------------
__device__ __forceinline__ uint32_t f2tf(float f) {
    uint32_t r;
    asm("cvt.rna.tf32.f32 %0, %1;" : "=r"(r) : "f"(f));
    return r;
}
__device__ __forceinline__ float rnd_tf32(float f) { return __uint_as_float(f2tf(f)); }

__device__ __forceinline__ void cp16(uint32_t saddr, const void* gaddr) {
    asm volatile("cp.async.cg.shared.global [%0], [%1], 16;" :: "r"(saddr), "l"(gaddr));
}

__device__ __forceinline__ void ldsm4(uint32_t r[4], uint32_t addr) {
    asm volatile("ldmatrix.sync.aligned.m8n8.x4.shared.b16 {%0,%1,%2,%3}, [%4];"
                 : "=r"(r[0]), "=r"(r[1]), "=r"(r[2]), "=r"(r[3]) : "r"(addr));
}

__device__ __forceinline__ void mma8(float c[4], const uint32_t a[4],
                                     uint32_t b0, uint32_t b1) {
    asm volatile(
        "mma.sync.aligned.m16n8k8.row.col.f32.tf32.tf32.f32 "
        "{%0,%1,%2,%3},{%4,%5,%6,%7},{%8,%9},{%0,%1,%2,%3};"
        : "+f"(c[0]), "+f"(c[1]), "+f"(c[2]), "+f"(c[3])
        : "r"(a[0]), "r"(a[1]), "r"(a[2]), "r"(a[3]), "r"(b0), "r"(b1));
}

// ---------------- kernel 0: zero counters ----------------
__global__ void init_kernel() {
    if (threadIdx.x < NEXP) g_cnt[threadIdx.x] = 0;
}

// ---------------- kernel 1: gate + routing + tf32-round x into g_X ----------------
__global__ void gate_kernel(const float* __restrict__ x,
                            const float* __restrict__ gw,
                            const float* __restrict__ gb) {
    __shared__ float sgw[NEXP * DIN];  // 32 KB
    const int t = threadIdx.x;
    for (int i = t; i < NEXP * DIN / 4; i += 256)
        ((float4*)sgw)[i] = ((const float4*)gw)[i];
    __syncthreads();

    const int warp = t >> 5, lane = t & 31;
    const int n = blockIdx.x * 8 + warp;

    float acc[NEXP];
#pragma unroll
    for (int e = 0; e < NEXP; e++) acc[e] = 0.f;

    const float* xr = x + (size_t)n * DIN;
    float* gxr = g_X + (size_t)n * DIN;
    for (int kk = 0; kk < DIN; kk += 32) {
        float xv = xr[kk + lane];
        gxr[kk + lane] = rnd_tf32(xv);      // fused pre-round for GEMM1's A
#pragma unroll
        for (int e = 0; e < NEXP; e++)
            acc[e] = fmaf(xv, sgw[e * DIN + kk + lane], acc[e]);
    }
#pragma unroll
    for (int off = 16; off; off >>= 1) {
#pragma unroll
        for (int e = 0; e < NEXP; e++)
            acc[e] += __shfl_xor_sync(0xffffffffu, acc[e], off);
    }

    if (lane == 0) {
        float lg[NEXP];
#pragma unroll
        for (int e = 0; e < NEXP; e++) lg[e] = acc[e] + gb[e];
        int e0 = 0;
#pragma unroll
        for (int e = 1; e < NEXP; e++) if (lg[e] > lg[e0]) e0 = e;
        int e1 = (e0 == 0) ? 1 : 0;
#pragma unroll
        for (int e = 0; e < NEXP; e++) if (e != e0 && lg[e] > lg[e1]) e1 = e;

        float z  = expf(lg[e1] - lg[e0]);
        float w0 = 1.f / (1.f + z);
        float w1 = z / (1.f + z);

        int s0 = atomicAdd(&g_cnt[e0], 1);
        int s1 = atomicAdd(&g_cnt[e1], 1);
        int r0 = e0 * CAP + s0;
        int r1 = e1 * CAP + s1;
        g_tok_of_row[r0] = n;
        g_tok_of_row[r1] = n;
        g_slot_row[2 * n]     = r0;
        g_slot_row[2 * n + 1] = r1;
        g_slot_w[2 * n]     = w0;
        g_slot_w[2 * n + 1] = w1;
    }
}

// ---------------- kernels 2/3: expert GEMMs (tf32 mma.sync + ldmatrix, pipelined) --
// MODE 1: H = relu( gather(g_X) @ W1[e]^T + b1[e] ), rounded to tf32  (K=1024, N=4096)
// MODE 2: Y =            g_H     @ W2[e]^T + b2[e]                    (K=4096, N=1024)
// Block 128x128xBK32, 256 threads (2x4 warps, 64x32 warp tiles), 3-stage cp.async,
// ldmatrix.x4 fragment loads with A-fragment software pipelining.
#define SM_PITCH  36
#define STAGES    3
#define STAGE_FL  (128 * SM_PITCH)              // 4608 floats
#define STAGE_BYT (STAGE_FL * 4)                // 18432 bytes
#define SMEM_BYTES (STAGES * 2 * STAGE_BYT)     // 110592 bytes
#define ROW32_SM  (32 * SM_PITCH * 4)           // 32 smem rows in bytes

template <int MODE>
__global__ void __launch_bounds__(256, 2) moe_gemm(const float* __restrict__ Wt,
                                                   const float* __restrict__ bias) {
    constexpr int KD = (MODE == 1) ? DIN : DHID;
    constexpr int ND = (MODE == 1) ? DHID : DOUT;
    constexpr int KT = KD / 32;
    constexpr size_t ROW32_G = (size_t)32 * KD;  // 32 global rows (floats)

    const int e  = blockIdx.z;
    const int m0 = blockIdx.y * 128;
    const int n0 = blockIdx.x * 128;
    const int cnt = g_cnt[e];
    if (m0 >= cnt) return;

    extern __shared__ char smc[];
    const uint32_t smbase = (uint32_t)__cvta_generic_to_shared(smc);
    const int t = threadIdx.x;
    const int lane = t & 31, warp = t >> 5;
    const int wm = warp >> 2, wn = warp & 3;         // 2 x 4 warp grid

    // ---- producer: thread t covers rows {prow, prow+32, prow+64, prow+96} ----
    const int prow = t >> 3;            // 0..31
    const int pcol = (t & 7) * 4;       // 0..28
    const uint32_t soff = (uint32_t)(prow * SM_PITCH + pcol) * 4u;

    const float* gB = Wt + ((size_t)e * ND + n0 + prow) * KD + pcol;
    const float* gA2 = nullptr;         // MODE 2: single strided pointer
    const float* gA1[4];                // MODE 1: gathered token pointers
    if (MODE == 1) {
#pragma unroll
        for (int j = 0; j < 4; j++) {
            int r = m0 + prow + 32 * j;
            int tok = (r < cnt) ? g_tok_of_row[e * CAP + r] : g_tok_of_row[e * CAP];
            gA1[j] = g_X + (size_t)tok * KD + pcol;
        }
    } else {
        gA2 = g_H + (size_t)(e * CAP + m0 + prow) * KD + pcol;
    }

    // ---- ldmatrix base addresses (bytes): row = base + (lane&15), col16 = lane>>4 ----
    const uint32_t lrow = (uint32_t)(lane & 15);
    const uint32_t lcol = (uint32_t)((lane >> 4) * 16);
    const uint32_t aAddr0 = smbase +
        (uint32_t)((wm * 64) + lrow) * (SM_PITCH * 4) + lcol;
    const uint32_t bAddr0 = smbase + (uint32_t)(STAGES * STAGE_BYT) +
        (uint32_t)((wn * 32) + lrow) * (SM_PITCH * 4) + lcol;

    float c[4][4][4];
#pragma unroll
    for (int am = 0; am < 4; am++)
#pragma unroll
        for (int bn = 0; bn < 4; bn++)
#pragma unroll
            for (int i = 0; i < 4; i++) c[am][bn][i] = 0.f;

    auto issue = [&](int kt, int s) {
        const int kof = kt * 32;
        const uint32_t ab = smbase + (uint32_t)(s * STAGE_BYT) + soff;
        const uint32_t bb = ab + (uint32_t)(STAGES * STAGE_BYT);
#pragma unroll
        for (int j = 0; j < 4; j++)
            cp16(ab + j * ROW32_SM,
                 (MODE == 1 ? gA1[j] : gA2 + j * ROW32_G) + kof);
#pragma unroll
        for (int j = 0; j < 4; j++)
            cp16(bb + j * ROW32_SM, gB + j * ROW32_G + kof);
        asm volatile("cp.async.commit_group;");
    };

    // prologue: stages 0,1 in flight
    issue(0, 0);
    issue(1, 1);
    asm volatile("cp.async.wait_group 1;");
    __syncthreads();

    for (int kt = 0; kt < KT; kt++) {
        const int s = kt % STAGES;
        if (kt + 2 < KT) issue(kt + 2, (kt + 2) % STAGES);
        else asm volatile("cp.async.commit_group;");   // keep group accounting

        const uint32_t aS = aAddr0 + (uint32_t)(s * STAGE_BYT);
        const uint32_t bS = bAddr0 + (uint32_t)(s * STAGE_BYT);

        // A-fragment software pipeline: ping-pong buffers
        uint32_t a[2][4][4];
#pragma unroll
        for (int am = 0; am < 4; am++)
            ldsm4(a[0][am], aS + am * (16 * SM_PITCH * 4));

#pragma unroll
        for (int sl = 0; sl < 4; sl++) {
            const int cur = sl & 1;
            // B: two ldsm.x4 cover all 4 bn-groups for this k-slice
            uint32_t b0[4], b1[4];
            ldsm4(b0, bS + sl * 32);
            ldsm4(b1, bS + 16 * (SM_PITCH * 4) + sl * 32);
            // prefetch next slice's A fragments before the MMA burst
            if (sl < 3) {
#pragma unroll
                for (int am = 0; am < 4; am++)
                    ldsm4(a[cur ^ 1][am], aS + am * (16 * SM_PITCH * 4) + (sl + 1) * 32);
            }
            // tf32-round B in registers (A already rounded in memory)
#pragma unroll
            for (int i = 0; i < 4; i++) {
                b0[i] = f2tf(__uint_as_float(b0[i]));
                b1[i] = f2tf(__uint_as_float(b1[i]));
            }
            // bn0:{b0[0],b0[2]} bn1:{b0[1],b0[3]} bn2:{b1[0],b1[2]} bn3:{b1[1],b1[3]}
#pragma unroll
            for (int am = 0; am < 4; am++) {
                mma8(c[am][0], a[cur][am], b0[0], b0[2]);
                mma8(c[am][1], a[cur][am], b0[1], b0[3]);
                mma8(c[am][2], a[cur][am], b1[0], b1[2]);
                mma8(c[am][3], a[cur][am], b1[1], b1[3]);
            }
        }

        if (kt + 1 < KT) {
            asm volatile("cp.async.wait_group 1;");
            __syncthreads();
        }
    }

    // ---- epilogue ----
    const int grp = lane >> 2, tig = lane & 3;
    const float* bv = bias + (size_t)e * ND + n0;
    float* Dst = (MODE == 1) ? g_H : g_Y;
#pragma unroll
    for (int bn = 0; bn < 4; bn++) {
        const int cg = wn * 32 + bn * 8 + tig * 2;
        const float b0v = bv[cg], b1v = bv[cg + 1];
#pragma unroll
        for (int am = 0; am < 4; am++) {
            const int rl = wm * 64 + am * 16 + grp;
            float v0 = c[am][bn][0] + b0v;
            float v1 = c[am][bn][1] + b1v;
            float v2 = c[am][bn][2] + b0v;
            float v3 = c[am][bn][3] + b1v;
            if (MODE == 1) {   // relu, then round so GEMM2's A needs no cvt
                v0 = rnd_tf32(fmaxf(v0, 0.f)); v1 = rnd_tf32(fmaxf(v1, 0.f));
                v2 = rnd_tf32(fmaxf(v2, 0.f)); v3 = rnd_tf32(fmaxf(v3, 0.f));
            }
            const size_t base0 = (size_t)(e * CAP + m0 + rl) * ND + n0 + cg;
            const size_t base1 = (size_t)(e * CAP + m0 + rl + 8) * ND + n0 + cg;
            *reinterpret_cast<float2*>(Dst + base0) = make_float2(v0, v1);
            *reinterpret_cast<float2*>(Dst + base1) = make_float2(v2, v3);
        }
    }
}

// ---------------- kernel 4: weighted combine ----------------
__global__ void combine_kernel(float* __restrict__ out) {
    const int n = blockIdx.x, t = threadIdx.x;
    const int r0 = g_slot_row[2 * n], r1 = g_slot_row[2 * n + 1];
    const float w0 = g_slot_w[2 * n], w1 = g_slot_w[2 * n + 1];
    const float4 a = reinterpret_cast<const float4*>(g_Y + (size_t)r0 * DOUT)[t];
    const float4 b = reinterpret_cast<const float4*>(g_Y + (size_t)r1 * DOUT)[t];
    float4 o;
    o.x = w0 * a.x + w1 * b.x;
    o.y = w0 * a.y + w1 * b.y;
    o.z = w0 * a.z + w1 * b.z;
    o.w = w0 * a.w + w1 * b.w;
    reinterpret_cast<float4*>(out + (size_t)n * DOUT)[t] = o;
}

// ---------------- launch ----------------
extern "C" void kernel_launch(void* const* d_in, const int* in_sizes, int n_in,
                              void* d_out, int out_size) {
    const float* x  = (const float*)d_in[0];
    const float* gw = (const float*)d_in[1];
    const float* gb = (const float*)d_in[2];
    const float* W1 = (const float*)d_in[3];
    const float* b1 = (const float*)d_in[4];
    const float* W2 = (const float*)d_in[5];
    const float* b2 = (const float*)d_in[6];
    float* out = (float*)d_out;

    cudaFuncSetAttribute(moe_gemm<1>, cudaFuncAttributeMaxDynamicSharedMemorySize, SMEM_BYTES);
    cudaFuncSetAttribute(moe_gemm<2>, cudaFuncAttributeMaxDynamicSharedMemorySize, SMEM_BYTES);

    init_kernel<<<1, 32>>>();
    gate_kernel<<<NTOK / 8, 256>>>(x, gw, gb);
    moe_gemm<1><<<dim3(DHID / 128, CAP / 128, NEXP), 256, SMEM_BYTES>>>(W1, b1);
    moe_gemm<2><<<dim3(DOUT / 128, CAP / 128, NEXP), 256, SMEM_BYTES>>>(W2, b2);
    combine_kernel<<<NTOK, 256>>>(out);
}